// round 1
// baseline (speedup 1.0000x reference)
#include <cuda_runtime.h>
#include <cuda_bf16.h>

// ChannelPolyLayer: out[b,o,x,y] = sum_c coeffs[b,o,c] * prod_v img[b,v,x,y]^powers[c,v]
// DEGREE=3, NUM_VARS=3, NUM_OUT=3, NUM_COEFFS=20, BATCH=16, H=W=512.
//
// Monomial order from _generate_powers(3,3) (hand-enumerated, deterministic):
//  0:1  1:v0  2:v1  3:v2  4:v0^2  5:v0v1  6:v0v2  7:v1^2  8:v1v2  9:v2^2
// 10:v0^3 11:v0^2v1 12:v0^2v2 13:v0v1^2 14:v0v1v2 15:v0v2^2
// 16:v1^3 17:v1^2v2 18:v1v2^2 19:v2^3

#define HW_PIX (512 * 512)
#define HW4 (HW_PIX / 4)
#define NBATCH 16
#define NCOEF 20

__device__ __forceinline__ void eval_pixel(float v0, float v1, float v2,
                                           const float* __restrict__ sc,
                                           float& r0, float& r1, float& r2) {
    float m[NCOEF];
    float v00 = v0 * v0, v11 = v1 * v1, v22 = v2 * v2;
    m[0] = 1.0f;
    m[1] = v0;        m[2] = v1;        m[3] = v2;
    m[4] = v00;       m[5] = v0 * v1;   m[6] = v0 * v2;
    m[7] = v11;       m[8] = v1 * v2;   m[9] = v22;
    m[10] = v00 * v0; m[11] = v00 * v1; m[12] = v00 * v2;
    m[13] = v0 * v11; m[14] = m[5] * v2; m[15] = v0 * v22;
    m[16] = v11 * v1; m[17] = v11 * v2; m[18] = v1 * v22; m[19] = v22 * v2;

    float a0 = 0.0f, a1 = 0.0f, a2 = 0.0f;
#pragma unroll
    for (int c = 0; c < NCOEF; c++) {
        a0 = fmaf(sc[c], m[c], a0);
        a1 = fmaf(sc[NCOEF + c], m[c], a1);
        a2 = fmaf(sc[2 * NCOEF + c], m[c], a2);
    }
    r0 = a0; r1 = a1; r2 = a2;
}

__global__ __launch_bounds__(256) void channel_poly_kernel(
    const float* __restrict__ img,     // (B, 3, H, W)
    const float* __restrict__ coeffs,  // (B, 3, 20)
    float* __restrict__ out)           // (B, 3, H, W)
{
    __shared__ float sc[3 * NCOEF];
    const int b = blockIdx.y;
    const int t = threadIdx.x;
    if (t < 3 * NCOEF) sc[t] = coeffs[b * (3 * NCOEF) + t];
    __syncthreads();

    const int i = blockIdx.x * blockDim.x + t;  // float4 index within one channel plane
    if (i >= HW4) return;

    const float4* __restrict__ in0 =
        reinterpret_cast<const float4*>(img + (size_t)b * 3 * HW_PIX);
    const float4 x0 = in0[i];
    const float4 x1 = in0[i + HW4];
    const float4 x2 = in0[i + 2 * HW4];

    float4 y0, y1, y2;
    eval_pixel(x0.x, x1.x, x2.x, sc, y0.x, y1.x, y2.x);
    eval_pixel(x0.y, x1.y, x2.y, sc, y0.y, y1.y, y2.y);
    eval_pixel(x0.z, x1.z, x2.z, sc, y0.z, y1.z, y2.z);
    eval_pixel(x0.w, x1.w, x2.w, sc, y0.w, y1.w, y2.w);

    float4* __restrict__ o = reinterpret_cast<float4*>(out + (size_t)b * 3 * HW_PIX);
    o[i] = y0;
    o[i + HW4] = y1;
    o[i + 2 * HW4] = y2;
}

extern "C" void kernel_launch(void* const* d_in, const int* in_sizes, int n_in,
                              void* d_out, int out_size) {
    const float* img = (const float*)d_in[0];     // (16,3,512,512)
    const float* coeffs = (const float*)d_in[1];  // (16,3,20)
    // d_in[2] = powers (16? no: 20x3) — order hardcoded above, not read.
    float* out = (float*)d_out;

    dim3 grid(HW4 / 256, NBATCH, 1);
    channel_poly_kernel<<<grid, 256>>>(img, coeffs, out);
}

// round 2
// speedup vs baseline: 1.5335x; 1.5335x over previous
#include <cuda_runtime.h>
#include <cuda_bf16.h>

// ChannelPolyLayer: out[b,o,x,y] = sum_c coeffs[b,o,c] * prod_v img[b,v,x,y]^powers[c,v]
// DEGREE=3, NUM_VARS=3, NUM_OUT=3, NUM_COEFFS=20, BATCH=16, H=W=512.
//
// Monomial order from _generate_powers(3,3):
//  0:1  1:v0  2:v1  3:v2  4:v0^2  5:v0v1  6:v0v2  7:v1^2  8:v1v2  9:v2^2
// 10:v0^3 11:v0^2v1 12:v0^2v2 13:v0v1^2 14:v0v1v2 15:v0v2^2
// 16:v1^3 17:v1^2v2 18:v1v2^2 19:v2^3
//
// Evaluated as nested Horner:
//   P = ((c10*v0 + C2)*v0 + C1)*v0 + C0
//   C2 = c4 + c11*v1 + c12*v2
//   C1 = (c15*v2 + (c6 + c14*v1))*v2 + (c1 + v1*(c5 + c13*v1))
//   C0 = ((c19*v2 + (c9 + c18*v1))*v2 + (c3 + v1*(c8 + c17*v1)))*v2
//        + (c0 + v1*(c2 + v1*(c7 + c16*v1)))
// 19 FMAs per output per pixel, only v0,v1,v2 live.

#define HW_PIX (512 * 512)
#define HW4 (HW_PIX / 4)
#define NBATCH 16
#define NCOEF 20

__device__ __forceinline__ float horner(float v0, float v1, float v2,
                                        const float* __restrict__ c) {
    // C0(v1,v2)
    float pA = fmaf(c[16], v1, c[7]);
    pA = fmaf(v1, pA, c[2]);
    pA = fmaf(v1, pA, c[0]);                 // c0 + c2 v1 + c7 v1^2 + c16 v1^3
    float pB = fmaf(c[17], v1, c[8]);
    pB = fmaf(v1, pB, c[3]);                 // c3 + c8 v1 + c17 v1^2
    float pC = fmaf(c[18], v1, c[9]);        // c9 + c18 v1
    float C0 = fmaf(c[19], v2, pC);
    C0 = fmaf(C0, v2, pB);
    C0 = fmaf(C0, v2, pA);
    // C1(v1,v2)
    float qA = fmaf(c[13], v1, c[5]);
    qA = fmaf(v1, qA, c[1]);                 // c1 + c5 v1 + c13 v1^2
    float qB = fmaf(c[14], v1, c[6]);        // c6 + c14 v1
    float C1 = fmaf(c[15], v2, qB);
    C1 = fmaf(C1, v2, qA);
    // C2(v1,v2)
    float C2 = fmaf(c[11], v1, c[4]);
    C2 = fmaf(c[12], v2, C2);
    // Horner in v0
    float r = fmaf(c[10], v0, C2);
    r = fmaf(r, v0, C1);
    r = fmaf(r, v0, C0);
    return r;
}

__global__ __launch_bounds__(256, 4) void channel_poly_kernel(
    const float* __restrict__ img,     // (B, 3, H, W)
    const float* __restrict__ coeffs,  // (B, 3, 20)
    float* __restrict__ out)           // (B, 3, H, W)
{
    __shared__ float sc[3 * NCOEF];
    const int b = blockIdx.y;
    const int t = threadIdx.x;
    if (t < 3 * NCOEF) sc[t] = coeffs[b * (3 * NCOEF) + t];
    __syncthreads();

    const int i = blockIdx.x * blockDim.x + t;  // float4 index within one channel plane

    const float4* __restrict__ in0 =
        reinterpret_cast<const float4*>(img + (size_t)b * 3 * HW_PIX);
    const float4 x0 = in0[i];
    const float4 x1 = in0[i + HW4];
    const float4 x2 = in0[i + 2 * HW4];

    float4* __restrict__ o = reinterpret_cast<float4*>(out + (size_t)b * 3 * HW_PIX);

#pragma unroll 1
    for (int oc = 0; oc < 3; oc++) {
        const float* __restrict__ c = sc + oc * NCOEF;
        float4 r;
        r.x = horner(x0.x, x1.x, x2.x, c);
        r.y = horner(x0.y, x1.y, x2.y, c);
        r.z = horner(x0.z, x1.z, x2.z, c);
        r.w = horner(x0.w, x1.w, x2.w, c);
        o[i + oc * HW4] = r;
    }
}

extern "C" void kernel_launch(void* const* d_in, const int* in_sizes, int n_in,
                              void* d_out, int out_size) {
    const float* img = (const float*)d_in[0];     // (16,3,512,512)
    const float* coeffs = (const float*)d_in[1];  // (16,3,20)
    float* out = (float*)d_out;

    dim3 grid(HW4 / 256, NBATCH, 1);
    channel_poly_kernel<<<grid, 256>>>(img, coeffs, out);
}